// round 6
// baseline (speedup 1.0000x reference)
#include <cuda_runtime.h>
#include <cuda_bf16.h>
#include <math_constants.h>

#define BATCH   2
#define SEQ     2048
#define NHEADS  16
#define DHEAD   128
#define DMODEL  2048
#define DM3     6144
#define MTOT    4096

// Scratch (device globals)
__device__ __nv_bfloat16 g_qkvh[(size_t)MTOT * DM3];
__device__ __nv_bfloat16 g_qkvl[(size_t)MTOT * DM3];
__device__ __nv_bfloat16 g_xh[(size_t)MTOT * DMODEL];
__device__ __nv_bfloat16 g_xl[(size_t)MTOT * DMODEL];
__device__ __nv_bfloat16 g_wqkvth[(size_t)DM3 * DMODEL];   // [N=6144][K=2048]
__device__ __nv_bfloat16 g_wqkvtl[(size_t)DM3 * DMODEL];
__device__ __nv_bfloat16 g_woutth[(size_t)DMODEL * DMODEL];
__device__ __nv_bfloat16 g_wouttl[(size_t)DMODEL * DMODEL];
__device__ __nv_bfloat16 g_attnh[(size_t)MTOT * DMODEL];
__device__ __nv_bfloat16 g_attnl[(size_t)MTOT * DMODEL];

// ---------------------------------------------------------------------------
// Helpers
// ---------------------------------------------------------------------------
static __device__ __forceinline__ void mma_bf16(
    float& c0, float& c1, float& c2, float& c3,
    unsigned a0, unsigned a1, unsigned a2, unsigned a3,
    unsigned b0, unsigned b1)
{
    asm volatile(
        "mma.sync.aligned.m16n8k16.row.col.f32.bf16.bf16.f32 "
        "{%0,%1,%2,%3}, {%4,%5,%6,%7}, {%8,%9}, {%0,%1,%2,%3};\n"
        : "+f"(c0), "+f"(c1), "+f"(c2), "+f"(c3)
        : "r"(a0), "r"(a1), "r"(a2), "r"(a3), "r"(b0), "r"(b1));
}
static __device__ __forceinline__ void ldsm_x4(
    unsigned& r0, unsigned& r1, unsigned& r2, unsigned& r3, unsigned addr)
{
    asm volatile("ldmatrix.sync.aligned.m8n8.x4.shared.b16 {%0,%1,%2,%3}, [%4];\n"
                 : "=r"(r0), "=r"(r1), "=r"(r2), "=r"(r3) : "r"(addr));
}
static __device__ __forceinline__ void ldsm_x4t(
    unsigned& r0, unsigned& r1, unsigned& r2, unsigned& r3, unsigned addr)
{
    asm volatile("ldmatrix.sync.aligned.m8n8.x4.trans.shared.b16 {%0,%1,%2,%3}, [%4];\n"
                 : "=r"(r0), "=r"(r1), "=r"(r2), "=r"(r3) : "r"(addr));
}
static __device__ __forceinline__ unsigned bf2u(__nv_bfloat162 v) {
    return *reinterpret_cast<unsigned*>(&v);
}
static __device__ __forceinline__ void split4(float4 f, uint2& hi, uint2& lo) {
    __nv_bfloat162 h0 = __floats2bfloat162_rn(f.x, f.y);
    __nv_bfloat162 h1 = __floats2bfloat162_rn(f.z, f.w);
    float hx = __low2float(h0), hy = __high2float(h0);
    float hz = __low2float(h1), hw = __high2float(h1);
    __nv_bfloat162 l0 = __floats2bfloat162_rn(f.x - hx, f.y - hy);
    __nv_bfloat162 l1 = __floats2bfloat162_rn(f.z - hz, f.w - hw);
    hi.x = bf2u(h0); hi.y = bf2u(h1);
    lo.x = bf2u(l0); lo.y = bf2u(l1);
}
static __device__ __forceinline__ void cpa16(unsigned saddr, const void* g) {
    asm volatile("cp.async.cg.shared.global [%0], [%1], 16;\n"
                 :: "r"(saddr), "l"(g));
}

// ---------------------------------------------------------------------------
// Prep kernels: fp32 -> bf16 hi/lo planes
// ---------------------------------------------------------------------------
__global__ __launch_bounds__(256) void split_rm_kernel(
    const float4* __restrict__ src, uint2* __restrict__ h, uint2* __restrict__ l,
    int n4)
{
    int i = blockIdx.x * 256 + threadIdx.x;
    if (i < n4) {
        uint2 hi, lo;
        split4(src[i], hi, lo);
        h[i] = hi; l[i] = lo;
    }
}

// W [K][N] fp32 -> Wt hi/lo [N][K] bf16
__global__ __launch_bounds__(256) void split_tr_kernel(
    const float* __restrict__ W,
    __nv_bfloat16* __restrict__ th, __nv_bfloat16* __restrict__ tl,
    int K, int N)
{
    __shared__ float tile[32][33];
    const int n0 = blockIdx.x * 32, k0 = blockIdx.y * 32;
    const int tx = threadIdx.x & 31, ty = threadIdx.x >> 5;  // 32 x 8
    #pragma unroll
    for (int i = 0; i < 32; i += 8)
        tile[ty + i][tx] = W[(size_t)(k0 + ty + i) * N + (n0 + tx)];
    __syncthreads();
    #pragma unroll
    for (int i = 0; i < 32; i += 8) {
        float v = tile[tx][ty + i];
        __nv_bfloat16 hb = __float2bfloat16(v);
        __nv_bfloat16 lb = __float2bfloat16(v - __bfloat162float(hb));
        size_t o = (size_t)(n0 + ty + i) * K + (k0 + tx);
        th[o] = hb; tl[o] = lb;
    }
}

// ---------------------------------------------------------------------------
// Plane GEMM: C = (Ah+Al)[M,K] @ (Bh+Bl)^T[N,K] + bias
// Block 128x128, ktile 32, 4-stage cp.async ring (wait_group 2),
// 256 threads = 8 warps (4m x 2n), warp tile 32m x 64n.
// Output: fp32 C (if Cf != nullptr) or bf16 hi/lo planes (Ch, Cl).
// ---------------------------------------------------------------------------
#define GST 40                       // halves per smem row (32 + 8 pad)
#define PLN (128 * GST)              // plane size in halves (5120)
#define BUFH (4 * PLN)               // stage stride in halves (20480)
#define STAGES 4
#define GEMM_SMEM_BYTES (STAGES * BUFH * 2)   // 163840

__global__ __launch_bounds__(256) void gemm_planes_bias_kernel(
    const __nv_bfloat16* __restrict__ Ah, const __nv_bfloat16* __restrict__ Al,
    const __nv_bfloat16* __restrict__ Bh, const __nv_bfloat16* __restrict__ Bl,
    const float* __restrict__ bias,
    float* __restrict__ Cf,
    __nv_bfloat16* __restrict__ Ch, __nv_bfloat16* __restrict__ Cl,
    int M, int N, int K)
{
    extern __shared__ __nv_bfloat16 sm[];
    const unsigned sb = (unsigned)__cvta_generic_to_shared(sm);

    const int t = threadIdx.x, lane = t & 31, wid = t >> 5;
    const int bm = blockIdx.y, bn = blockIdx.x;
    const int warp_m = wid >> 1, warp_n = wid & 1;

    const int lr = t >> 1;
    const int ls = (t & 1) * 16;
    const __nv_bfloat16* Ahg = Ah + (size_t)(bm * 128 + lr) * K + ls;
    const __nv_bfloat16* Alg = Al + (size_t)(bm * 128 + lr) * K + ls;
    const __nv_bfloat16* Bhg = Bh + (size_t)(bn * 128 + lr) * K + ls;
    const __nv_bfloat16* Blg = Bl + (size_t)(bn * 128 + lr) * K + ls;
    const unsigned sAd = sb + 2 * (lr * GST + ls);

    float c[2][8][4];
    #pragma unroll
    for (int mf = 0; mf < 2; mf++)
        #pragma unroll
        for (int nf = 0; nf < 8; nf++)
            #pragma unroll
            for (int i = 0; i < 4; i++) c[mf][nf][i] = 0.f;

    const int nK = K / 32;

    // Issue one k-tile stage
    auto issue_stage = [&](int kt) {
        const int go = kt * 32;
        unsigned d = sAd + 2 * (kt % STAGES) * BUFH;
        cpa16(d,                 Ahg + go);
        cpa16(d + 16,            Ahg + go + 8);
        cpa16(d + 2 * PLN,       Alg + go);
        cpa16(d + 2 * PLN + 16,  Alg + go + 8);
        cpa16(d + 4 * PLN,       Bhg + go);
        cpa16(d + 4 * PLN + 16,  Bhg + go + 8);
        cpa16(d + 6 * PLN,       Blg + go);
        cpa16(d + 6 * PLN + 16,  Blg + go + 8);
        asm volatile("cp.async.commit_group;\n" ::: "memory");
    };

    // Prologue: 3 stages in flight
    #pragma unroll
    for (int kt = 0; kt < 3; kt++) issue_stage(kt);

    for (int kt = 0; kt < nK; kt++) {
        asm volatile("cp.async.wait_group 2;\n" ::: "memory");
        __syncthreads();

        if (kt + 3 < nK) issue_stage(kt + 3);

        const unsigned base = sb + 2 * (kt % STAGES) * BUFH;
        #pragma unroll
        for (int s = 0; s < 2; s++) {
            unsigned ah[2][4], al[2][4];
            #pragma unroll
            for (int mf = 0; mf < 2; mf++) {
                const int row = warp_m * 32 + mf * 16 + (lane & 15);
                const unsigned a = base + 2 * (row * GST + 16 * s + 8 * (lane >> 4));
                ldsm_x4(ah[mf][0], ah[mf][1], ah[mf][2], ah[mf][3], a);
                ldsm_x4(al[mf][0], al[mf][1], al[mf][2], al[mf][3], a + 2 * PLN);
            }
            #pragma unroll
            for (int nfp = 0; nfp < 4; nfp++) {
                const int nrow = warp_n * 64 + nfp * 16 + (lane & 7) + 8 * (lane >> 4);
                const unsigned a = base + 2 * (2 * PLN + nrow * GST
                                               + 16 * s + 8 * ((lane >> 3) & 1));
                unsigned bh0, bh1, bh2, bh3, bl0, bl1, bl2, bl3;
                ldsm_x4(bh0, bh1, bh2, bh3, a);
                ldsm_x4(bl0, bl1, bl2, bl3, a + 2 * PLN);
                #pragma unroll
                for (int mf = 0; mf < 2; mf++) {
                    float* c0 = c[mf][2 * nfp];
                    float* c1 = c[mf][2 * nfp + 1];
                    mma_bf16(c0[0], c0[1], c0[2], c0[3],
                             ah[mf][0], ah[mf][1], ah[mf][2], ah[mf][3], bh0, bh1);
                    mma_bf16(c0[0], c0[1], c0[2], c0[3],
                             al[mf][0], al[mf][1], al[mf][2], al[mf][3], bh0, bh1);
                    mma_bf16(c0[0], c0[1], c0[2], c0[3],
                             ah[mf][0], ah[mf][1], ah[mf][2], ah[mf][3], bl0, bl1);
                    mma_bf16(c1[0], c1[1], c1[2], c1[3],
                             ah[mf][0], ah[mf][1], ah[mf][2], ah[mf][3], bh2, bh3);
                    mma_bf16(c1[0], c1[1], c1[2], c1[3],
                             al[mf][0], al[mf][1], al[mf][2], al[mf][3], bh2, bh3);
                    mma_bf16(c1[0], c1[1], c1[2], c1[3],
                             ah[mf][0], ah[mf][1], ah[mf][2], ah[mf][3], bl2, bl3);
                }
            }
        }
        __syncthreads();
    }

    // Epilogue
    const int g = lane >> 2, q = lane & 3;
    const int crow0 = bm * 128 + warp_m * 32 + g;
    const int ccol0 = bn * 128 + warp_n * 64 + 2 * q;
    if (Cf) {
        #pragma unroll
        for (int nf = 0; nf < 8; nf++) {
            const int col = ccol0 + nf * 8;
            const float bx = bias[col];
            const float by = bias[col + 1];
            #pragma unroll
            for (int mf = 0; mf < 2; mf++) {
                const int row = crow0 + mf * 16;
                *(float2*)(Cf + (size_t)row * N + col) =
                    make_float2(c[mf][nf][0] + bx, c[mf][nf][1] + by);
                *(float2*)(Cf + (size_t)(row + 8) * N + col) =
                    make_float2(c[mf][nf][2] + bx, c[mf][nf][3] + by);
            }
        }
    } else {
        unsigned* Chu = (unsigned*)Ch;
        unsigned* Clu = (unsigned*)Cl;
        const int nh = N / 2;
        #pragma unroll
        for (int nf = 0; nf < 8; nf++) {
            const int col = ccol0 + nf * 8;
            const float bx = bias[col];
            const float by = bias[col + 1];
            #pragma unroll
            for (int mf = 0; mf < 2; mf++) {
                const int row = crow0 + mf * 16;
                float v0 = c[mf][nf][0] + bx, v1 = c[mf][nf][1] + by;
                float w0 = c[mf][nf][2] + bx, w1 = c[mf][nf][3] + by;
                __nv_bfloat162 vh = __floats2bfloat162_rn(v0, v1);
                __nv_bfloat162 wh = __floats2bfloat162_rn(w0, w1);
                __nv_bfloat162 vl = __floats2bfloat162_rn(v0 - __low2float(vh),
                                                          v1 - __high2float(vh));
                __nv_bfloat162 wl = __floats2bfloat162_rn(w0 - __low2float(wh),
                                                          w1 - __high2float(wh));
                Chu[(size_t)row * nh + col / 2]       = bf2u(vh);
                Clu[(size_t)row * nh + col / 2]       = bf2u(vl);
                Chu[(size_t)(row + 8) * nh + col / 2] = bf2u(wh);
                Clu[(size_t)(row + 8) * nh + col / 2] = bf2u(wl);
            }
        }
    }
}

// ---------------------------------------------------------------------------
// Tensor-core flash attention (causal), triple-bf16.
// Inputs: qkv hi/lo bf16 planes ([MTOT][DM3] each). Outputs bf16 hi/lo planes.
// ---------------------------------------------------------------------------
#define ATT_C 0.12751666769323707f  // (1/sqrt(128)) * log2(e)
#define RSTR  136
#define QH_OFF 0
#define QL_OFF 17408
#define KH_OFF 34816
#define KL_OFF 43520
#define VH_OFF 52224
#define VL_OFF 60928
#define ATT_SMEM_BYTES (69632 * 2)

__global__ __launch_bounds__(256) void flash_attn_tc_kernel(
    const __nv_bfloat16* __restrict__ qkvh, const __nv_bfloat16* __restrict__ qkvl,
    __nv_bfloat16* __restrict__ outh, __nv_bfloat16* __restrict__ outl)
{
    extern __shared__ unsigned smu[];
    const unsigned sbase = (unsigned)__cvta_generic_to_shared(smu);

    const int qblk = blockIdx.x;
    const int h    = blockIdx.y;
    const int b    = blockIdx.z;
    const int tid  = threadIdx.x;
    const int lane = tid & 31;
    const int w    = tid >> 5;
    const int g    = lane >> 2;
    const int q    = lane & 3;

    // ---- Load Q tile (128 rows x 128 halves per plane)
    {
        const int r  = tid >> 1;
        const int c0 = (tid & 1) * 64;   // halves
        const size_t gofs = (size_t)(b * SEQ + qblk * 128 + r) * DM3 + h * DHEAD + c0;
        const uint4* qhp = (const uint4*)(qkvh + gofs);
        const uint4* qlp = (const uint4*)(qkvl + gofs);
        #pragma unroll
        for (int i = 0; i < 8; i++) {   // 8 x uint4 = 64 halves
            const int hofs = r * RSTR + c0 + 8 * i;
            *(uint4*)(smu + (QH_OFF + hofs) / 2) = qhp[i];
            *(uint4*)(smu + (QL_OFF + hofs) / 2) = qlp[i];
        }
    }
    __syncthreads();

    unsigned qh[8][4], ql[8][4];
    {
        const int row = 16 * w + (lane & 15);
        const int cb  = 8 * (lane >> 4);
        #pragma unroll
        for (int ds = 0; ds < 8; ds++) {
            unsigned a = sbase + 2 * (QH_OFF + row * RSTR + 16 * ds + cb);
            ldsm_x4(qh[ds][0], qh[ds][1], qh[ds][2], qh[ds][3], a);
            ldsm_x4(ql[ds][0], ql[ds][1], ql[ds][2], ql[ds][3],
                    a + 2 * (QL_OFF - QH_OFF));
        }
    }

    float o[16][4];
    #pragma unroll
    for (int nf = 0; nf < 16; nf++)
        #pragma unroll
        for (int i = 0; i < 4; i++) o[nf][i] = 0.f;
    float m0 = -1e30f, m1 = -1e30f, l0 = 0.f, l1 = 0.f;

    const int ntiles = 2 * qblk + 2;
    const int warp_row_max = qblk * 128 + 16 * w + 15;

    for (int kt = 0; kt < ntiles; kt++) {
        __syncthreads();
        // ---- Load K,V tile (64 rows x 128 halves per plane)
        {
            const int r  = tid >> 2;
            const int c0 = (tid & 3) * 32;   // halves
            const size_t kofs = (size_t)(b * SEQ + kt * 64 + r) * DM3
                                + h * DHEAD + DMODEL + c0;
            const uint4* khp = (const uint4*)(qkvh + kofs);
            const uint4* klp = (const uint4*)(qkvl + kofs);
            const uint4* vhp = (const uint4*)(qkvh + kofs + DMODEL);
            const uint4* vlp = (const uint4*)(qkvl + kofs + DMODEL);
            #pragma unroll
            for (int i = 0; i < 4; i++) {   // 4 x uint4 = 32 halves
                const int hofs = r * RSTR + c0 + 8 * i;
                *(uint4*)(smu + (KH_OFF + hofs) / 2) = khp[i];
                *(uint4*)(smu + (KL_OFF + hofs) / 2) = klp[i];
                *(uint4*)(smu + (VH_OFF + hofs) / 2) = vhp[i];
                *(uint4*)(smu + (VL_OFF + hofs) / 2) = vlp[i];
            }
        }
        __syncthreads();

        if (kt * 64 > warp_row_max) continue;

        float s[8][4];
        #pragma unroll
        for (int nf = 0; nf < 8; nf++)
            #pragma unroll
            for (int i = 0; i < 4; i++) s[nf][i] = 0.f;

        {
            const int krow   = (lane & 7) + 8 * (lane >> 4);
            const int kchunk = 8 * ((lane >> 3) & 1);
            #pragma unroll
            for (int ds = 0; ds < 8; ds++) {
                #pragma unroll
                for (int nfp = 0; nfp < 4; nfp++) {
                    unsigned a = sbase + 2 * (KH_OFF + (16 * nfp + krow) * RSTR
                                              + 16 * ds + kchunk);
                    unsigned bh0, bh1, bh2, bh3, bl0, bl1, bl2, bl3;
                    ldsm_x4(bh0, bh1, bh2, bh3, a);
                    ldsm_x4(bl0, bl1, bl2, bl3, a + 2 * (KL_OFF - KH_OFF));
                    float* s0 = s[2 * nfp];
                    float* s1 = s[2 * nfp + 1];
                    mma_bf16(s0[0], s0[1], s0[2], s0[3],
                             qh[ds][0], qh[ds][1], qh[ds][2], qh[ds][3], bh0, bh1);
                    mma_bf16(s0[0], s0[1], s0[2], s0[3],
                             ql[ds][0], ql[ds][1], ql[ds][2], ql[ds][3], bh0, bh1);
                    mma_bf16(s0[0], s0[1], s0[2], s0[3],
                             qh[ds][0], qh[ds][1], qh[ds][2], qh[ds][3], bl0, bl1);
                    mma_bf16(s1[0], s1[1], s1[2], s1[3],
                             qh[ds][0], qh[ds][1], qh[ds][2], qh[ds][3], bh2, bh3);
                    mma_bf16(s1[0], s1[1], s1[2], s1[3],
                             ql[ds][0], ql[ds][1], ql[ds][2], ql[ds][3], bh2, bh3);
                    mma_bf16(s1[0], s1[1], s1[2], s1[3],
                             qh[ds][0], qh[ds][1], qh[ds][2], qh[ds][3], bl2, bl3);
                }
            }
        }

        if (kt >= 2 * qblk) {
            const int row0 = qblk * 128 + 16 * w + g;
            #pragma unroll
            for (int nf = 0; nf < 8; nf++) {
                const int col = kt * 64 + 8 * nf + 2 * q;
                if (col     > row0)     s[nf][0] = -CUDART_INF_F;
                if (col + 1 > row0)     s[nf][1] = -CUDART_INF_F;
                if (col     > row0 + 8) s[nf][2] = -CUDART_INF_F;
                if (col + 1 > row0 + 8) s[nf][3] = -CUDART_INF_F;
            }
        }

        float tm0 = -CUDART_INF_F, tm1 = -CUDART_INF_F;
        #pragma unroll
        for (int nf = 0; nf < 8; nf++) {
            tm0 = fmaxf(tm0, fmaxf(s[nf][0], s[nf][1]));
            tm1 = fmaxf(tm1, fmaxf(s[nf][2], s[nf][3]));
        }
        tm0 = fmaxf(tm0, __shfl_xor_sync(0xffffffffu, tm0, 1));
        tm0 = fmaxf(tm0, __shfl_xor_sync(0xffffffffu, tm0, 2));
        tm1 = fmaxf(tm1, __shfl_xor_sync(0xffffffffu, tm1, 1));
        tm1 = fmaxf(tm1, __shfl_xor_sync(0xffffffffu, tm1, 2));

        const float m0n = fmaxf(m0, tm0);
        const float m1n = fmaxf(m1, tm1);
        const float cr0 = exp2f((m0 - m0n) * ATT_C);
        const float cr1 = exp2f((m1 - m1n) * ATT_C);
        m0 = m0n; m1 = m1n;
        l0 *= cr0; l1 *= cr1;
        #pragma unroll
        for (int nf = 0; nf < 16; nf++) {
            o[nf][0] *= cr0; o[nf][1] *= cr0;
            o[nf][2] *= cr1; o[nf][3] *= cr1;
        }

        unsigned ph[8][2], pl[8][2];
        #pragma unroll
        for (int nf = 0; nf < 8; nf++) {
            float p0 = exp2f((s[nf][0] - m0) * ATT_C);
            float p1 = exp2f((s[nf][1] - m0) * ATT_C);
            float p2 = exp2f((s[nf][2] - m1) * ATT_C);
            float p3 = exp2f((s[nf][3] - m1) * ATT_C);
            l0 += p0 + p1;
            l1 += p2 + p3;
            __nv_bfloat162 h01 = __floats2bfloat162_rn(p0, p1);
            __nv_bfloat162 h23 = __floats2bfloat162_rn(p2, p3);
            __nv_bfloat162 e01 = __floats2bfloat162_rn(p0 - __low2float(h01),
                                                       p1 - __high2float(h01));
            __nv_bfloat162 e23 = __floats2bfloat162_rn(p2 - __low2float(h23),
                                                       p3 - __high2float(h23));
            ph[nf][0] = bf2u(h01); ph[nf][1] = bf2u(h23);
            pl[nf][0] = bf2u(e01); pl[nf][1] = bf2u(e23);
        }

        {
            const int vrow   = (lane & 15);
            const int vchunk = 8 * (lane >> 4);
            #pragma unroll
            for (int j = 0; j < 4; j++) {
                const unsigned ah0 = ph[2 * j][0],     ah1 = ph[2 * j][1];
                const unsigned ah2 = ph[2 * j + 1][0], ah3 = ph[2 * j + 1][1];
                const unsigned al0 = pl[2 * j][0],     al1 = pl[2 * j][1];
                const unsigned al2 = pl[2 * j + 1][0], al3 = pl[2 * j + 1][1];
                #pragma unroll
                for (int nfp = 0; nfp < 8; nfp++) {
                    unsigned a = sbase + 2 * (VH_OFF + (16 * j + vrow) * RSTR
                                              + 16 * nfp + vchunk);
                    unsigned vh0, vh1, vh2, vh3, vl0, vl1, vl2, vl3;
                    ldsm_x4t(vh0, vh1, vh2, vh3, a);
                    ldsm_x4t(vl0, vl1, vl2, vl3, a + 2 * (VL_OFF - VH_OFF));
                    float* o0 = o[2 * nfp];
                    float* o1 = o[2 * nfp + 1];
                    mma_bf16(o0[0], o0[1], o0[2], o0[3], ah0, ah1, ah2, ah3, vh0, vh1);
                    mma_bf16(o0[0], o0[1], o0[2], o0[3], al0, al1, al2, al3, vh0, vh1);
                    mma_bf16(o0[0], o0[1], o0[2], o0[3], ah0, ah1, ah2, ah3, vl0, vl1);
                    mma_bf16(o1[0], o1[1], o1[2], o1[3], ah0, ah1, ah2, ah3, vh2, vh3);
                    mma_bf16(o1[0], o1[1], o1[2], o1[3], al0, al1, al2, al3, vh2, vh3);
                    mma_bf16(o1[0], o1[1], o1[2], o1[3], ah0, ah1, ah2, ah3, vl2, vl3);
                }
            }
        }
    }

    l0 += __shfl_xor_sync(0xffffffffu, l0, 1);
    l0 += __shfl_xor_sync(0xffffffffu, l0, 2);
    l1 += __shfl_xor_sync(0xffffffffu, l1, 1);
    l1 += __shfl_xor_sync(0xffffffffu, l1, 2);
    const float inv0 = 1.f / l0;
    const float inv1 = 1.f / l1;

    const size_t row0 = (size_t)(b * SEQ + qblk * 128 + 16 * w + g);
    unsigned* obh = (unsigned*)(outh + row0 * DMODEL + h * DHEAD);
    unsigned* obl = (unsigned*)(outl + row0 * DMODEL + h * DHEAD);
    #pragma unroll
    for (int nf = 0; nf < 16; nf++) {
        const int ci = 4 * nf + q;
        float x0 = o[nf][0] * inv0, x1 = o[nf][1] * inv0;
        float y0 = o[nf][2] * inv1, y1 = o[nf][3] * inv1;
        __nv_bfloat162 xh = __floats2bfloat162_rn(x0, x1);
        __nv_bfloat162 yh = __floats2bfloat162_rn(y0, y1);
        __nv_bfloat162 xl = __floats2bfloat162_rn(x0 - __low2float(xh),
                                                  x1 - __high2float(xh));
        __nv_bfloat162 yl = __floats2bfloat162_rn(y0 - __low2float(yh),
                                                  y1 - __high2float(yh));
        obh[ci] = bf2u(xh);
        obl[ci] = bf2u(xl);
        obh[ci + 4 * DMODEL] = bf2u(yh);
        obl[ci + 4 * DMODEL] = bf2u(yl);
    }
}

// ---------------------------------------------------------------------------
// kernel_launch
// ---------------------------------------------------------------------------
extern "C" void kernel_launch(void* const* d_in, const int* in_sizes, int n_in,
                              void* d_out, int out_size)
{
    const float* x     = (const float*)d_in[0];
    const float* W_qkv = (const float*)d_in[1];
    const float* b_qkv = (const float*)d_in[2];
    const float* W_out = (const float*)d_in[3];
    const float* b_out = (const float*)d_in[4];
    float* out = (float*)d_out;

    __nv_bfloat16 *qh, *ql, *xh, *xl, *wqh, *wql, *woh, *wol, *ath, *atl;
    cudaGetSymbolAddress((void**)&qh,  g_qkvh);
    cudaGetSymbolAddress((void**)&ql,  g_qkvl);
    cudaGetSymbolAddress((void**)&xh,  g_xh);
    cudaGetSymbolAddress((void**)&xl,  g_xl);
    cudaGetSymbolAddress((void**)&wqh, g_wqkvth);
    cudaGetSymbolAddress((void**)&wql, g_wqkvtl);
    cudaGetSymbolAddress((void**)&woh, g_woutth);
    cudaGetSymbolAddress((void**)&wol, g_wouttl);
    cudaGetSymbolAddress((void**)&ath, g_attnh);
    cudaGetSymbolAddress((void**)&atl, g_attnl);

    cudaFuncSetAttribute(flash_attn_tc_kernel,
                         cudaFuncAttributeMaxDynamicSharedMemorySize,
                         ATT_SMEM_BYTES);
    cudaFuncSetAttribute(gemm_planes_bias_kernel,
                         cudaFuncAttributeMaxDynamicSharedMemorySize,
                         GEMM_SMEM_BYTES);

    // Prep
    split_rm_kernel<<<(MTOT * DMODEL / 4 + 255) / 256, 256>>>(
        (const float4*)x, (uint2*)xh, (uint2*)xl, MTOT * DMODEL / 4);
    split_tr_kernel<<<dim3(DM3 / 32, DMODEL / 32), 256>>>(
        W_qkv, wqh, wql, DMODEL, DM3);
    split_tr_kernel<<<dim3(DMODEL / 32, DMODEL / 32), 256>>>(
        W_out, woh, wol, DMODEL, DMODEL);

    // 1) QKV GEMM -> bf16 hi/lo planes
    gemm_planes_bias_kernel<<<dim3(DM3 / 128, MTOT / 128), 256, GEMM_SMEM_BYTES>>>(
        xh, xl, wqh, wql, b_qkv, nullptr, qh, ql, MTOT, DM3, DMODEL);

    // 2) Flash attention (plane inputs) -> bf16 hi/lo planes
    flash_attn_tc_kernel<<<dim3(16, NHEADS, BATCH), 256, ATT_SMEM_BYTES>>>(
        qh, ql, ath, atl);

    // 3) Output GEMM -> fp32
    gemm_planes_bias_kernel<<<dim3(DMODEL / 128, MTOT / 128), 256, GEMM_SMEM_BYTES>>>(
        ath, atl, woh, wol, b_out, out, nullptr, nullptr, MTOT, DMODEL, DMODEL);
}

// round 7
// speedup vs baseline: 1.0820x; 1.0820x over previous
#include <cuda_runtime.h>
#include <cuda_bf16.h>
#include <math_constants.h>

#define BATCH   2
#define SEQ     2048
#define NHEADS  16
#define DHEAD   128
#define DMODEL  2048
#define DM3     6144
#define MTOT    4096

// Scratch (device globals)
__device__ __nv_bfloat16 g_qkvh[(size_t)MTOT * DM3];
__device__ __nv_bfloat16 g_qkvl[(size_t)MTOT * DM3];
__device__ __nv_bfloat16 g_xh[(size_t)MTOT * DMODEL];
__device__ __nv_bfloat16 g_xl[(size_t)MTOT * DMODEL];
__device__ __nv_bfloat16 g_wqkvth[(size_t)DM3 * DMODEL];   // [N=6144][K=2048]
__device__ __nv_bfloat16 g_wqkvtl[(size_t)DM3 * DMODEL];
__device__ __nv_bfloat16 g_woutth[(size_t)DMODEL * DMODEL];
__device__ __nv_bfloat16 g_wouttl[(size_t)DMODEL * DMODEL];
__device__ __nv_bfloat16 g_attnh[(size_t)MTOT * DMODEL];
__device__ __nv_bfloat16 g_attnl[(size_t)MTOT * DMODEL];

// ---------------------------------------------------------------------------
// Helpers
// ---------------------------------------------------------------------------
static __device__ __forceinline__ void mma_bf16(
    float& c0, float& c1, float& c2, float& c3,
    unsigned a0, unsigned a1, unsigned a2, unsigned a3,
    unsigned b0, unsigned b1)
{
    asm volatile(
        "mma.sync.aligned.m16n8k16.row.col.f32.bf16.bf16.f32 "
        "{%0,%1,%2,%3}, {%4,%5,%6,%7}, {%8,%9}, {%0,%1,%2,%3};\n"
        : "+f"(c0), "+f"(c1), "+f"(c2), "+f"(c3)
        : "r"(a0), "r"(a1), "r"(a2), "r"(a3), "r"(b0), "r"(b1));
}
static __device__ __forceinline__ void ldsm_x4(
    unsigned& r0, unsigned& r1, unsigned& r2, unsigned& r3, unsigned addr)
{
    asm volatile("ldmatrix.sync.aligned.m8n8.x4.shared.b16 {%0,%1,%2,%3}, [%4];\n"
                 : "=r"(r0), "=r"(r1), "=r"(r2), "=r"(r3) : "r"(addr));
}
static __device__ __forceinline__ void ldsm_x4t(
    unsigned& r0, unsigned& r1, unsigned& r2, unsigned& r3, unsigned addr)
{
    asm volatile("ldmatrix.sync.aligned.m8n8.x4.trans.shared.b16 {%0,%1,%2,%3}, [%4];\n"
                 : "=r"(r0), "=r"(r1), "=r"(r2), "=r"(r3) : "r"(addr));
}
static __device__ __forceinline__ unsigned bf2u(__nv_bfloat162 v) {
    return *reinterpret_cast<unsigned*>(&v);
}
static __device__ __forceinline__ void split4(float4 f, uint2& hi, uint2& lo) {
    __nv_bfloat162 h0 = __floats2bfloat162_rn(f.x, f.y);
    __nv_bfloat162 h1 = __floats2bfloat162_rn(f.z, f.w);
    float hx = __low2float(h0), hy = __high2float(h0);
    float hz = __low2float(h1), hw = __high2float(h1);
    __nv_bfloat162 l0 = __floats2bfloat162_rn(f.x - hx, f.y - hy);
    __nv_bfloat162 l1 = __floats2bfloat162_rn(f.z - hz, f.w - hw);
    hi.x = bf2u(h0); hi.y = bf2u(h1);
    lo.x = bf2u(l0); lo.y = bf2u(l1);
}
static __device__ __forceinline__ void cpa16(unsigned saddr, const void* g) {
    asm volatile("cp.async.cg.shared.global [%0], [%1], 16;\n"
                 :: "r"(saddr), "l"(g));
}

// ---------------------------------------------------------------------------
// Prep kernels: fp32 -> bf16 hi/lo planes
// ---------------------------------------------------------------------------
__global__ __launch_bounds__(256) void split_rm_kernel(
    const float4* __restrict__ src, uint2* __restrict__ h, uint2* __restrict__ l,
    int n4)
{
    int i = blockIdx.x * 256 + threadIdx.x;
    if (i < n4) {
        uint2 hi, lo;
        split4(src[i], hi, lo);
        h[i] = hi; l[i] = lo;
    }
}

// W [K][N] fp32 -> Wt hi/lo [N][K] bf16
__global__ __launch_bounds__(256) void split_tr_kernel(
    const float* __restrict__ W,
    __nv_bfloat16* __restrict__ th, __nv_bfloat16* __restrict__ tl,
    int K, int N)
{
    __shared__ float tile[32][33];
    const int n0 = blockIdx.x * 32, k0 = blockIdx.y * 32;
    const int tx = threadIdx.x & 31, ty = threadIdx.x >> 5;  // 32 x 8
    #pragma unroll
    for (int i = 0; i < 32; i += 8)
        tile[ty + i][tx] = W[(size_t)(k0 + ty + i) * N + (n0 + tx)];
    __syncthreads();
    #pragma unroll
    for (int i = 0; i < 32; i += 8) {
        float v = tile[tx][ty + i];
        __nv_bfloat16 hb = __float2bfloat16(v);
        __nv_bfloat16 lb = __float2bfloat16(v - __bfloat162float(hb));
        size_t o = (size_t)(n0 + ty + i) * K + (k0 + tx);
        th[o] = hb; tl[o] = lb;
    }
}

// ---------------------------------------------------------------------------
// Plane GEMM: C = (Ah+Al)[M,K] @ (Bh+Bl)^T[N,K] + bias
// Block tile 256x128, ktile 32, 512 threads = 16 warps (8m x 2n),
// warp tile 32x64. 3-stage cp.async ring, wait_group 1 (2-tile prefetch).
// Output: fp32 C (Cf != nullptr) or bf16 hi/lo planes (Ch, Cl).
// ---------------------------------------------------------------------------
#define GST 40                         // halves per smem row (32 + 8 pad)
#define APLN (256 * GST)               // A plane halves (10240)
#define BPLN (128 * GST)               // B plane halves (5120)
#define AH_O 0
#define AL_O APLN
#define BH_O (2 * APLN)
#define BL_O (2 * APLN + BPLN)
#define STAGE_H (2 * APLN + 2 * BPLN)  // 30720 halves = 61440 B
#define GSTAGES 3
#define GEMM_SMEM_BYTES (GSTAGES * STAGE_H * 2)   // 184320

__global__ __launch_bounds__(512) void gemm_planes_bias_kernel(
    const __nv_bfloat16* __restrict__ Ah, const __nv_bfloat16* __restrict__ Al,
    const __nv_bfloat16* __restrict__ Bh, const __nv_bfloat16* __restrict__ Bl,
    const float* __restrict__ bias,
    float* __restrict__ Cf,
    __nv_bfloat16* __restrict__ Ch, __nv_bfloat16* __restrict__ Cl,
    int M, int N, int K)
{
    extern __shared__ __nv_bfloat16 sm[];
    const unsigned sb = (unsigned)__cvta_generic_to_shared(sm);

    const int t = threadIdx.x, lane = t & 31, wid = t >> 5;
    const int bm = blockIdx.y, bn = blockIdx.x;
    const int warp_m = wid >> 1, warp_n = wid & 1;   // 8 x 2

    // cp.async assignments
    const int ar  = t >> 1;            // A row 0..255
    const int as  = (t & 1) * 16;      // A halves offset (two 16B chunks)
    const int br  = t >> 2;            // B row 0..127
    const int bs  = (t & 3) * 8;       // B halves offset (one 16B chunk)
    const __nv_bfloat16* Ahg = Ah + (size_t)(bm * 256 + ar) * K + as;
    const __nv_bfloat16* Alg = Al + (size_t)(bm * 256 + ar) * K + as;
    const __nv_bfloat16* Bhg = Bh + (size_t)(bn * 128 + br) * K + bs;
    const __nv_bfloat16* Blg = Bl + (size_t)(bn * 128 + br) * K + bs;
    const unsigned sA = sb + 2 * (ar * GST + as);
    const unsigned sB = sb + 2 * (br * GST + bs);

    float c[2][8][4];
    #pragma unroll
    for (int mf = 0; mf < 2; mf++)
        #pragma unroll
        for (int nf = 0; nf < 8; nf++)
            #pragma unroll
            for (int i = 0; i < 4; i++) c[mf][nf][i] = 0.f;

    const int nK = K / 32;

    auto issue_stage = [&](int kt) {
        const int go = kt * 32;
        const unsigned so = 2 * (kt % GSTAGES) * STAGE_H;
        cpa16(sA + so + 2 * AH_O,       Ahg + go);
        cpa16(sA + so + 2 * AH_O + 16,  Ahg + go + 8);
        cpa16(sA + so + 2 * AL_O,       Alg + go);
        cpa16(sA + so + 2 * AL_O + 16,  Alg + go + 8);
        cpa16(sB + so + 2 * BH_O,       Bhg + go);
        cpa16(sB + so + 2 * BL_O,       Blg + go);
        asm volatile("cp.async.commit_group;\n" ::: "memory");
    };

    issue_stage(0);
    issue_stage(1);

    for (int kt = 0; kt < nK; kt++) {
        asm volatile("cp.async.wait_group 1;\n" ::: "memory");
        __syncthreads();

        if (kt + 2 < nK) issue_stage(kt + 2);

        const unsigned base = sb + 2 * (kt % GSTAGES) * STAGE_H;
        #pragma unroll
        for (int s = 0; s < 2; s++) {
            unsigned ah[2][4], al[2][4];
            #pragma unroll
            for (int mf = 0; mf < 2; mf++) {
                const int row = warp_m * 32 + mf * 16 + (lane & 15);
                const unsigned a = base + 2 * (AH_O + row * GST + 16 * s + 8 * (lane >> 4));
                ldsm_x4(ah[mf][0], ah[mf][1], ah[mf][2], ah[mf][3], a);
                ldsm_x4(al[mf][0], al[mf][1], al[mf][2], al[mf][3],
                        a + 2 * (AL_O - AH_O));
            }
            #pragma unroll
            for (int nfp = 0; nfp < 4; nfp++) {
                const int nrow = warp_n * 64 + nfp * 16 + (lane & 7) + 8 * (lane >> 4);
                const unsigned a = base + 2 * (BH_O + nrow * GST
                                               + 16 * s + 8 * ((lane >> 3) & 1));
                unsigned bh0, bh1, bh2, bh3, bl0, bl1, bl2, bl3;
                ldsm_x4(bh0, bh1, bh2, bh3, a);
                ldsm_x4(bl0, bl1, bl2, bl3, a + 2 * (BL_O - BH_O));
                #pragma unroll
                for (int mf = 0; mf < 2; mf++) {
                    float* c0 = c[mf][2 * nfp];
                    float* c1 = c[mf][2 * nfp + 1];
                    mma_bf16(c0[0], c0[1], c0[2], c0[3],
                             ah[mf][0], ah[mf][1], ah[mf][2], ah[mf][3], bh0, bh1);
                    mma_bf16(c0[0], c0[1], c0[2], c0[3],
                             al[mf][0], al[mf][1], al[mf][2], al[mf][3], bh0, bh1);
                    mma_bf16(c0[0], c0[1], c0[2], c0[3],
                             ah[mf][0], ah[mf][1], ah[mf][2], ah[mf][3], bl0, bl1);
                    mma_bf16(c1[0], c1[1], c1[2], c1[3],
                             ah[mf][0], ah[mf][1], ah[mf][2], ah[mf][3], bh2, bh3);
                    mma_bf16(c1[0], c1[1], c1[2], c1[3],
                             al[mf][0], al[mf][1], al[mf][2], al[mf][3], bh2, bh3);
                    mma_bf16(c1[0], c1[1], c1[2], c1[3],
                             ah[mf][0], ah[mf][1], ah[mf][2], ah[mf][3], bl2, bl3);
                }
            }
        }
    }

    // Epilogue
    const int g = lane >> 2, q = lane & 3;
    const int crow0 = bm * 256 + warp_m * 32 + g;
    const int ccol0 = bn * 128 + warp_n * 64 + 2 * q;
    if (Cf) {
        #pragma unroll
        for (int nf = 0; nf < 8; nf++) {
            const int col = ccol0 + nf * 8;
            const float bx = bias[col];
            const float by = bias[col + 1];
            #pragma unroll
            for (int mf = 0; mf < 2; mf++) {
                const int row = crow0 + mf * 16;
                *(float2*)(Cf + (size_t)row * N + col) =
                    make_float2(c[mf][nf][0] + bx, c[mf][nf][1] + by);
                *(float2*)(Cf + (size_t)(row + 8) * N + col) =
                    make_float2(c[mf][nf][2] + bx, c[mf][nf][3] + by);
            }
        }
    } else {
        unsigned* Chu = (unsigned*)Ch;
        unsigned* Clu = (unsigned*)Cl;
        const int nh = N / 2;
        #pragma unroll
        for (int nf = 0; nf < 8; nf++) {
            const int col = ccol0 + nf * 8;
            const float bx = bias[col];
            const float by = bias[col + 1];
            #pragma unroll
            for (int mf = 0; mf < 2; mf++) {
                const int row = crow0 + mf * 16;
                float v0 = c[mf][nf][0] + bx, v1 = c[mf][nf][1] + by;
                float w0 = c[mf][nf][2] + bx, w1 = c[mf][nf][3] + by;
                __nv_bfloat162 vh = __floats2bfloat162_rn(v0, v1);
                __nv_bfloat162 wh = __floats2bfloat162_rn(w0, w1);
                __nv_bfloat162 vl = __floats2bfloat162_rn(v0 - __low2float(vh),
                                                          v1 - __high2float(vh));
                __nv_bfloat162 wl = __floats2bfloat162_rn(w0 - __low2float(wh),
                                                          w1 - __high2float(wh));
                Chu[(size_t)row * nh + col / 2]       = bf2u(vh);
                Clu[(size_t)row * nh + col / 2]       = bf2u(vl);
                Chu[(size_t)(row + 8) * nh + col / 2] = bf2u(wh);
                Clu[(size_t)(row + 8) * nh + col / 2] = bf2u(wl);
            }
        }
    }
}

// ---------------------------------------------------------------------------
// Tensor-core flash attention (causal), triple-bf16. Plane in, plane out.
// ---------------------------------------------------------------------------
#define ATT_C 0.12751666769323707f  // (1/sqrt(128)) * log2(e)
#define RSTR  136
#define QH_OFF 0
#define QL_OFF 17408
#define KH_OFF 34816
#define KL_OFF 43520
#define VH_OFF 52224
#define VL_OFF 60928
#define ATT_SMEM_BYTES (69632 * 2)

__global__ __launch_bounds__(256) void flash_attn_tc_kernel(
    const __nv_bfloat16* __restrict__ qkvh, const __nv_bfloat16* __restrict__ qkvl,
    __nv_bfloat16* __restrict__ outh, __nv_bfloat16* __restrict__ outl)
{
    extern __shared__ unsigned smu[];
    const unsigned sbase = (unsigned)__cvta_generic_to_shared(smu);

    const int qblk = blockIdx.x;
    const int h    = blockIdx.y;
    const int b    = blockIdx.z;
    const int tid  = threadIdx.x;
    const int lane = tid & 31;
    const int w    = tid >> 5;
    const int g    = lane >> 2;
    const int q    = lane & 3;

    {
        const int r  = tid >> 1;
        const int c0 = (tid & 1) * 64;
        const size_t gofs = (size_t)(b * SEQ + qblk * 128 + r) * DM3 + h * DHEAD + c0;
        const uint4* qhp = (const uint4*)(qkvh + gofs);
        const uint4* qlp = (const uint4*)(qkvl + gofs);
        #pragma unroll
        for (int i = 0; i < 8; i++) {
            const int hofs = r * RSTR + c0 + 8 * i;
            *(uint4*)(smu + (QH_OFF + hofs) / 2) = qhp[i];
            *(uint4*)(smu + (QL_OFF + hofs) / 2) = qlp[i];
        }
    }
    __syncthreads();

    unsigned qh[8][4], ql[8][4];
    {
        const int row = 16 * w + (lane & 15);
        const int cb  = 8 * (lane >> 4);
        #pragma unroll
        for (int ds = 0; ds < 8; ds++) {
            unsigned a = sbase + 2 * (QH_OFF + row * RSTR + 16 * ds + cb);
            ldsm_x4(qh[ds][0], qh[ds][1], qh[ds][2], qh[ds][3], a);
            ldsm_x4(ql[ds][0], ql[ds][1], ql[ds][2], ql[ds][3],
                    a + 2 * (QL_OFF - QH_OFF));
        }
    }

    float o[16][4];
    #pragma unroll
    for (int nf = 0; nf < 16; nf++)
        #pragma unroll
        for (int i = 0; i < 4; i++) o[nf][i] = 0.f;
    float m0 = -1e30f, m1 = -1e30f, l0 = 0.f, l1 = 0.f;

    const int ntiles = 2 * qblk + 2;
    const int warp_row_max = qblk * 128 + 16 * w + 15;

    for (int kt = 0; kt < ntiles; kt++) {
        __syncthreads();
        {
            const int r  = tid >> 2;
            const int c0 = (tid & 3) * 32;
            const size_t kofs = (size_t)(b * SEQ + kt * 64 + r) * DM3
                                + h * DHEAD + DMODEL + c0;
            const uint4* khp = (const uint4*)(qkvh + kofs);
            const uint4* klp = (const uint4*)(qkvl + kofs);
            const uint4* vhp = (const uint4*)(qkvh + kofs + DMODEL);
            const uint4* vlp = (const uint4*)(qkvl + kofs + DMODEL);
            #pragma unroll
            for (int i = 0; i < 4; i++) {
                const int hofs = r * RSTR + c0 + 8 * i;
                *(uint4*)(smu + (KH_OFF + hofs) / 2) = khp[i];
                *(uint4*)(smu + (KL_OFF + hofs) / 2) = klp[i];
                *(uint4*)(smu + (VH_OFF + hofs) / 2) = vhp[i];
                *(uint4*)(smu + (VL_OFF + hofs) / 2) = vlp[i];
            }
        }
        __syncthreads();

        if (kt * 64 > warp_row_max) continue;

        float s[8][4];
        #pragma unroll
        for (int nf = 0; nf < 8; nf++)
            #pragma unroll
            for (int i = 0; i < 4; i++) s[nf][i] = 0.f;

        {
            const int krow   = (lane & 7) + 8 * (lane >> 4);
            const int kchunk = 8 * ((lane >> 3) & 1);
            #pragma unroll
            for (int ds = 0; ds < 8; ds++) {
                #pragma unroll
                for (int nfp = 0; nfp < 4; nfp++) {
                    unsigned a = sbase + 2 * (KH_OFF + (16 * nfp + krow) * RSTR
                                              + 16 * ds + kchunk);
                    unsigned bh0, bh1, bh2, bh3, bl0, bl1, bl2, bl3;
                    ldsm_x4(bh0, bh1, bh2, bh3, a);
                    ldsm_x4(bl0, bl1, bl2, bl3, a + 2 * (KL_OFF - KH_OFF));
                    float* s0 = s[2 * nfp];
                    float* s1 = s[2 * nfp + 1];
                    mma_bf16(s0[0], s0[1], s0[2], s0[3],
                             qh[ds][0], qh[ds][1], qh[ds][2], qh[ds][3], bh0, bh1);
                    mma_bf16(s0[0], s0[1], s0[2], s0[3],
                             ql[ds][0], ql[ds][1], ql[ds][2], ql[ds][3], bh0, bh1);
                    mma_bf16(s0[0], s0[1], s0[2], s0[3],
                             qh[ds][0], qh[ds][1], qh[ds][2], qh[ds][3], bl0, bl1);
                    mma_bf16(s1[0], s1[1], s1[2], s1[3],
                             qh[ds][0], qh[ds][1], qh[ds][2], qh[ds][3], bh2, bh3);
                    mma_bf16(s1[0], s1[1], s1[2], s1[3],
                             ql[ds][0], ql[ds][1], ql[ds][2], ql[ds][3], bh2, bh3);
                    mma_bf16(s1[0], s1[1], s1[2], s1[3],
                             qh[ds][0], qh[ds][1], qh[ds][2], qh[ds][3], bl2, bl3);
                }
            }
        }

        if (kt >= 2 * qblk) {
            const int row0 = qblk * 128 + 16 * w + g;
            #pragma unroll
            for (int nf = 0; nf < 8; nf++) {
                const int col = kt * 64 + 8 * nf + 2 * q;
                if (col     > row0)     s[nf][0] = -CUDART_INF_F;
                if (col + 1 > row0)     s[nf][1] = -CUDART_INF_F;
                if (col     > row0 + 8) s[nf][2] = -CUDART_INF_F;
                if (col + 1 > row0 + 8) s[nf][3] = -CUDART_INF_F;
            }
        }

        float tm0 = -CUDART_INF_F, tm1 = -CUDART_INF_F;
        #pragma unroll
        for (int nf = 0; nf < 8; nf++) {
            tm0 = fmaxf(tm0, fmaxf(s[nf][0], s[nf][1]));
            tm1 = fmaxf(tm1, fmaxf(s[nf][2], s[nf][3]));
        }
        tm0 = fmaxf(tm0, __shfl_xor_sync(0xffffffffu, tm0, 1));
        tm0 = fmaxf(tm0, __shfl_xor_sync(0xffffffffu, tm0, 2));
        tm1 = fmaxf(tm1, __shfl_xor_sync(0xffffffffu, tm1, 1));
        tm1 = fmaxf(tm1, __shfl_xor_sync(0xffffffffu, tm1, 2));

        const float m0n = fmaxf(m0, tm0);
        const float m1n = fmaxf(m1, tm1);
        const float cr0 = exp2f((m0 - m0n) * ATT_C);
        const float cr1 = exp2f((m1 - m1n) * ATT_C);
        m0 = m0n; m1 = m1n;
        l0 *= cr0; l1 *= cr1;
        #pragma unroll
        for (int nf = 0; nf < 16; nf++) {
            o[nf][0] *= cr0; o[nf][1] *= cr0;
            o[nf][2] *= cr1; o[nf][3] *= cr1;
        }

        unsigned ph[8][2], pl[8][2];
        #pragma unroll
        for (int nf = 0; nf < 8; nf++) {
            float p0 = exp2f((s[nf][0] - m0) * ATT_C);
            float p1 = exp2f((s[nf][1] - m0) * ATT_C);
            float p2 = exp2f((s[nf][2] - m1) * ATT_C);
            float p3 = exp2f((s[nf][3] - m1) * ATT_C);
            l0 += p0 + p1;
            l1 += p2 + p3;
            __nv_bfloat162 h01 = __floats2bfloat162_rn(p0, p1);
            __nv_bfloat162 h23 = __floats2bfloat162_rn(p2, p3);
            __nv_bfloat162 e01 = __floats2bfloat162_rn(p0 - __low2float(h01),
                                                       p1 - __high2float(h01));
            __nv_bfloat162 e23 = __floats2bfloat162_rn(p2 - __low2float(h23),
                                                       p3 - __high2float(h23));
            ph[nf][0] = bf2u(h01); ph[nf][1] = bf2u(h23);
            pl[nf][0] = bf2u(e01); pl[nf][1] = bf2u(e23);
        }

        {
            const int vrow   = (lane & 15);
            const int vchunk = 8 * (lane >> 4);
            #pragma unroll
            for (int j = 0; j < 4; j++) {
                const unsigned ah0 = ph[2 * j][0],     ah1 = ph[2 * j][1];
                const unsigned ah2 = ph[2 * j + 1][0], ah3 = ph[2 * j + 1][1];
                const unsigned al0 = pl[2 * j][0],     al1 = pl[2 * j][1];
                const unsigned al2 = pl[2 * j + 1][0], al3 = pl[2 * j + 1][1];
                #pragma unroll
                for (int nfp = 0; nfp < 8; nfp++) {
                    unsigned a = sbase + 2 * (VH_OFF + (16 * j + vrow) * RSTR
                                              + 16 * nfp + vchunk);
                    unsigned vh0, vh1, vh2, vh3, vl0, vl1, vl2, vl3;
                    ldsm_x4t(vh0, vh1, vh2, vh3, a);
                    ldsm_x4t(vl0, vl1, vl2, vl3, a + 2 * (VL_OFF - VH_OFF));
                    float* o0 = o[2 * nfp];
                    float* o1 = o[2 * nfp + 1];
                    mma_bf16(o0[0], o0[1], o0[2], o0[3], ah0, ah1, ah2, ah3, vh0, vh1);
                    mma_bf16(o0[0], o0[1], o0[2], o0[3], al0, al1, al2, al3, vh0, vh1);
                    mma_bf16(o0[0], o0[1], o0[2], o0[3], ah0, ah1, ah2, ah3, vl0, vl1);
                    mma_bf16(o1[0], o1[1], o1[2], o1[3], ah0, ah1, ah2, ah3, vh2, vh3);
                    mma_bf16(o1[0], o1[1], o1[2], o1[3], al0, al1, al2, al3, vh2, vh3);
                    mma_bf16(o1[0], o1[1], o1[2], o1[3], ah0, ah1, ah2, ah3, vl2, vl3);
                }
            }
        }
    }

    l0 += __shfl_xor_sync(0xffffffffu, l0, 1);
    l0 += __shfl_xor_sync(0xffffffffu, l0, 2);
    l1 += __shfl_xor_sync(0xffffffffu, l1, 1);
    l1 += __shfl_xor_sync(0xffffffffu, l1, 2);
    const float inv0 = 1.f / l0;
    const float inv1 = 1.f / l1;

    const size_t row0 = (size_t)(b * SEQ + qblk * 128 + 16 * w + g);
    unsigned* obh = (unsigned*)(outh + row0 * DMODEL + h * DHEAD);
    unsigned* obl = (unsigned*)(outl + row0 * DMODEL + h * DHEAD);
    #pragma unroll
    for (int nf = 0; nf < 16; nf++) {
        const int ci = 4 * nf + q;
        float x0 = o[nf][0] * inv0, x1 = o[nf][1] * inv0;
        float y0 = o[nf][2] * inv1, y1 = o[nf][3] * inv1;
        __nv_bfloat162 xh = __floats2bfloat162_rn(x0, x1);
        __nv_bfloat162 yh = __floats2bfloat162_rn(y0, y1);
        __nv_bfloat162 xl = __floats2bfloat162_rn(x0 - __low2float(xh),
                                                  x1 - __high2float(xh));
        __nv_bfloat162 yl = __floats2bfloat162_rn(y0 - __low2float(yh),
                                                  y1 - __high2float(yh));
        obh[ci] = bf2u(xh);
        obl[ci] = bf2u(xl);
        obh[ci + 4 * DMODEL] = bf2u(yh);
        obl[ci + 4 * DMODEL] = bf2u(yl);
    }
}

// ---------------------------------------------------------------------------
// kernel_launch
// ---------------------------------------------------------------------------
extern "C" void kernel_launch(void* const* d_in, const int* in_sizes, int n_in,
                              void* d_out, int out_size)
{
    const float* x     = (const float*)d_in[0];
    const float* W_qkv = (const float*)d_in[1];
    const float* b_qkv = (const float*)d_in[2];
    const float* W_out = (const float*)d_in[3];
    const float* b_out = (const float*)d_in[4];
    float* out = (float*)d_out;

    __nv_bfloat16 *qh, *ql, *xh, *xl, *wqh, *wql, *woh, *wol, *ath, *atl;
    cudaGetSymbolAddress((void**)&qh,  g_qkvh);
    cudaGetSymbolAddress((void**)&ql,  g_qkvl);
    cudaGetSymbolAddress((void**)&xh,  g_xh);
    cudaGetSymbolAddress((void**)&xl,  g_xl);
    cudaGetSymbolAddress((void**)&wqh, g_wqkvth);
    cudaGetSymbolAddress((void**)&wql, g_wqkvtl);
    cudaGetSymbolAddress((void**)&woh, g_woutth);
    cudaGetSymbolAddress((void**)&wol, g_wouttl);
    cudaGetSymbolAddress((void**)&ath, g_attnh);
    cudaGetSymbolAddress((void**)&atl, g_attnl);

    cudaFuncSetAttribute(flash_attn_tc_kernel,
                         cudaFuncAttributeMaxDynamicSharedMemorySize,
                         ATT_SMEM_BYTES);
    cudaFuncSetAttribute(gemm_planes_bias_kernel,
                         cudaFuncAttributeMaxDynamicSharedMemorySize,
                         GEMM_SMEM_BYTES);

    // Prep
    split_rm_kernel<<<(MTOT * DMODEL / 4 + 255) / 256, 256>>>(
        (const float4*)x, (uint2*)xh, (uint2*)xl, MTOT * DMODEL / 4);
    split_tr_kernel<<<dim3(DM3 / 32, DMODEL / 32), 256>>>(
        W_qkv, wqh, wql, DMODEL, DM3);
    split_tr_kernel<<<dim3(DMODEL / 32, DMODEL / 32), 256>>>(
        W_out, woh, wol, DMODEL, DMODEL);

    // 1) QKV GEMM -> bf16 hi/lo planes
    gemm_planes_bias_kernel<<<dim3(DM3 / 128, MTOT / 256), 512, GEMM_SMEM_BYTES>>>(
        xh, xl, wqh, wql, b_qkv, nullptr, qh, ql, MTOT, DM3, DMODEL);

    // 2) Flash attention (plane inputs) -> bf16 hi/lo planes
    flash_attn_tc_kernel<<<dim3(16, NHEADS, BATCH), 256, ATT_SMEM_BYTES>>>(
        qh, ql, ath, atl);

    // 3) Output GEMM -> fp32
    gemm_planes_bias_kernel<<<dim3(DMODEL / 128, MTOT / 256), 512, GEMM_SMEM_BYTES>>>(
        ath, atl, woh, wol, b_out, out, nullptr, nullptr, MTOT, DMODEL, DMODEL);
}